// round 12
// baseline (speedup 1.0000x reference)
#include <cuda_runtime.h>
#include <cuda_bf16.h>
#include <math.h>
#include <stdint.h>

// ---------------- problem constants ----------------
#define N_ROWS     8192
#define DIM        256
#define NUM_PIDS   5532
#define NUM_CQ     5000
#define L_TOT      (NUM_PIDS + NUM_CQ)   // 10532
#define IGNORE_IDX 5554
#define OIM_SCALAR 30.0f
#define LOG2E      1.4426950408889634f
#define LN2F       0.6931471805599453f

// ---------------- tiling ----------------
#define BM 128
#define BN 128
#define BK 32
#define NSTAGE 4
#define NCB ((L_TOT + BN - 1) / BN)      // 83 column blocks
#define B_PAD (NCB * BN)                 // 10624 padded bank rows
#define NPAD (B_PAD - L_TOT)             // 92 padded cols, all in last block
#define ASTRIDE 40                       // bf16 elems per smem row (32 + 8 pad)

// dynamic smem layout (bytes)
#define STAGE_BYTES (BM * ASTRIDE * 2)          // 10240
#define OFF_SMA  0
#define OFF_SMB  (NSTAGE * STAGE_BYTES)         // 40960
#define OFF_REL  (2 * NSTAGE * STAGE_BYTES)     // 81920
#define OFF_LBL  (OFF_REL + BN * 4)             // 82432
#define OFF_RED  (OFF_LBL + BM * 4)             // 82944
#define SMEM_TOTAL (OFF_RED + BM * 4 * 4)       // 84992

// ---------------- device scratch (zero-initialized globals) ----------------
__device__ __nv_bfloat16 g_Abf[N_ROWS * DIM];
__device__ __nv_bfloat16 g_Bbf[B_PAD * DIM];   // rows >= L_TOT stay 0 forever
__device__ float g_partial[NCB][N_ROWS];
__device__ float g_labellogit2[N_ROWS];        // label logit in log2 units
__device__ float g_bsum[32];
__device__ float g_bcnt[32];
__device__ unsigned int g_ticket;              // starts 0, reset by last block

// ---------------- PTX helpers (sm_80+, valid under compute_100) ----------
__device__ __forceinline__ uint32_t smem_u32(const void* p) {
    uint32_t a;
    asm("{ .reg .u64 t; cvta.to.shared.u64 t, %1; cvt.u32.u64 %0, t; }"
        : "=r"(a) : "l"(p));
    return a;
}
__device__ __forceinline__ void cp_async16(uint32_t dst, const void* src) {
    asm volatile("cp.async.cg.shared.global [%0], [%1], 16;"
                 :: "r"(dst), "l"(src) : "memory");
}
__device__ __forceinline__ void cp_commit() {
    asm volatile("cp.async.commit_group;" ::: "memory");
}
template <int N>
__device__ __forceinline__ void cp_wait() {
    asm volatile("cp.async.wait_group %0;" :: "n"(N) : "memory");
}
__device__ __forceinline__ void ldsm_x4(uint32_t* r, uint32_t addr) {
    asm volatile("ldmatrix.sync.aligned.m8n8.x4.shared.b16 {%0,%1,%2,%3}, [%4];"
                 : "=r"(r[0]), "=r"(r[1]), "=r"(r[2]), "=r"(r[3]) : "r"(addr));
}
__device__ __forceinline__ void mma16816(float* d, const uint32_t* a, const uint32_t* b) {
    asm volatile(
        "mma.sync.aligned.m16n8k16.row.col.f32.bf16.bf16.f32 "
        "{%0,%1,%2,%3}, {%4,%5,%6,%7}, {%8,%9}, {%0,%1,%2,%3};"
        : "+f"(d[0]), "+f"(d[1]), "+f"(d[2]), "+f"(d[3])
        : "r"(a[0]), "r"(a[1]), "r"(a[2]), "r"(a[3]), "r"(b[0]), "r"(b[1]));
}
__device__ __forceinline__ float ex2f(float x) {
    float r;
    asm("ex2.approx.f32 %0, %1;" : "=f"(r) : "f"(x));
    return r;
}

// ---------------------------------------------------------------------------
// Kernel 0: fp32 -> bf16 conversion, 4 independent float4 chunks per thread
// ---------------------------------------------------------------------------
#define A_F4   (N_ROWS * DIM / 4)          // 524288
#define LUT_F4 (NUM_PIDS * DIM / 4)        // 354048
#define CQ_F4  (NUM_CQ * DIM / 4)          // 320000
#define TOT_F4 (A_F4 + LUT_F4 + CQ_F4)     // 1198336
#define QTR_F4 (TOT_F4 / 4)                // 299584

__device__ __forceinline__ void cvt_one(int i, const float* A,
                                        const float* lut, const float* cq) {
    const float4* src;
    __nv_bfloat16* dst;
    if (i < A_F4) {
        src = (const float4*)A + i;
        dst = g_Abf + (size_t)i * 4;
    } else if (i < A_F4 + LUT_F4) {
        int j = i - A_F4;
        src = (const float4*)lut + j;
        dst = g_Bbf + (size_t)j * 4;
    } else {
        int j = i - A_F4 - LUT_F4;
        src = (const float4*)cq + j;
        dst = g_Bbf + (size_t)(LUT_F4 + j) * 4;
    }
    float4 v = *src;
    ushort4 o;
    o.x = __bfloat16_as_ushort(__float2bfloat16_rn(v.x));
    o.y = __bfloat16_as_ushort(__float2bfloat16_rn(v.y));
    o.z = __bfloat16_as_ushort(__float2bfloat16_rn(v.z));
    o.w = __bfloat16_as_ushort(__float2bfloat16_rn(v.w));
    *reinterpret_cast<ushort4*>(dst) = o;
}

__global__ void cvt_kernel(const float* __restrict__ A,
                           const float* __restrict__ lut,
                           const float* __restrict__ cq) {
    int i = blockIdx.x * blockDim.x + threadIdx.x;
    if (i >= QTR_F4) return;
    cvt_one(i, A, lut, cq);
    cvt_one(i + QTR_F4, A, lut, cq);
    cvt_one(i + 2 * QTR_F4, A, lut, cq);
    cvt_one(i + 3 * QTR_F4, A, lut, cq);
}

// ---------------------------------------------------------------------------
// Kernel 1: mma.sync bf16 GEMM, 4-stage cp.async pipeline, fused exp-rowsum
// (R11 GEMM; epilogue: exp2 prefold + unguarded pad-corrected accumulation)
// ---------------------------------------------------------------------------
__global__ __launch_bounds__(256)
void oim_mma_kernel(const float* __restrict__ rel, const int* __restrict__ label)
{
    extern __shared__ __align__(16) char smem[];
    float* relS = (float*)(smem + OFF_REL);   // rel * 30 * log2e
    int*   lblS = (int*)(smem + OFF_LBL);
    float* red  = (float*)(smem + OFF_RED);

    const int tid = threadIdx.x;
    const int wid = tid >> 5;
    const int lane = tid & 31;
    const int warp_row = wid >> 2;        // 0..1
    const int warp_col = wid & 3;         // 0..3
    const int g = lane >> 2;
    const int t = lane & 3;

    const int bn = blockIdx.x;            // 0..82
    const int bm = blockIdx.y;            // 0..63
    const int row0 = bm * BM;
    const int col0 = bn * BN;

    if (tid < BN) {
        int c = col0 + tid;
        relS[tid] = (c < L_TOT) ? rel[c] * (OIM_SCALAR * LOG2E) : 0.0f;
    }
    if (tid < BM) lblS[tid] = label[row0 + tid];

    const uint32_t smA_u = smem_u32(smem + OFF_SMA);
    const uint32_t smB_u = smem_u32(smem + OFF_SMB);

    const int c0i = tid, c1i = tid + 256;
    const int m0 = c0i >> 2, ko0 = (c0i & 3) * 8;
    const int m1 = c1i >> 2, ko1 = (c1i & 3) * 8;
    const uint32_t dstA0 = smA_u + (uint32_t)(m0 * ASTRIDE + ko0) * 2;
    const uint32_t dstA1 = smA_u + (uint32_t)(m1 * ASTRIDE + ko1) * 2;
    const uint32_t dstB0 = smB_u + (uint32_t)(m0 * ASTRIDE + ko0) * 2;
    const uint32_t dstB1 = smB_u + (uint32_t)(m1 * ASTRIDE + ko1) * 2;
    const __nv_bfloat16* srcA0 = g_Abf + (size_t)(row0 + m0) * DIM + ko0;
    const __nv_bfloat16* srcA1 = g_Abf + (size_t)(row0 + m1) * DIM + ko1;
    const __nv_bfloat16* srcB0 = g_Bbf + (size_t)(col0 + m0) * DIM + ko0;
    const __nv_bfloat16* srcB1 = g_Bbf + (size_t)(col0 + m1) * DIM + ko1;

    // A ldmatrix x4: row = warp_row*64 + (lane&15), kofs = (lane>>4)*8
    const uint32_t aOff = smA_u +
        (uint32_t)(((warp_row * 64 + (lane & 15)) * ASTRIDE) + ((lane >> 4) << 3)) * 2;
    // B ldmatrix x4 (two n8 blocks per load)
    const uint32_t bOff = smB_u +
        (uint32_t)(((warp_col * 32 + (lane & 7) + ((lane & 16) >> 1)) * ASTRIDE)
                   + (((lane >> 3) & 1) << 3)) * 2;

    float acc[4][4][4];
#pragma unroll
    for (int mi = 0; mi < 4; mi++)
#pragma unroll
        for (int ni = 0; ni < 4; ni++)
#pragma unroll
            for (int h = 0; h < 4; h++)
                acc[mi][ni][h] = 0.0f;

    // prologue: prefetch stages 0..2
#pragma unroll
    for (int s = 0; s < NSTAGE - 1; s++) {
        const uint32_t so = (uint32_t)s * STAGE_BYTES;
        const int gko = s * BK;
        cp_async16(dstA0 + so, srcA0 + gko);
        cp_async16(dstA1 + so, srcA1 + gko);
        cp_async16(dstB0 + so, srcB0 + gko);
        cp_async16(dstB1 + so, srcB1 + gko);
        cp_commit();
    }

#pragma unroll
    for (int kc = 0; kc < 8; kc++) {
        if (kc <= 5)      cp_wait<2>();
        else if (kc == 6) cp_wait<1>();
        else              cp_wait<0>();
        __syncthreads();

        if (kc < 5) {
            const uint32_t so = (uint32_t)((kc + 3) & (NSTAGE - 1)) * STAGE_BYTES;
            const int gko = (kc + 3) * BK;
            cp_async16(dstA0 + so, srcA0 + gko);
            cp_async16(dstA1 + so, srcA1 + gko);
            cp_async16(dstB0 + so, srcB0 + gko);
            cp_async16(dstB1 + so, srcB1 + gko);
            cp_commit();
        }

        const uint32_t so = (uint32_t)(kc & (NSTAGE - 1)) * STAGE_BYTES;
        const uint32_t aBase = aOff + so;
        const uint32_t bBase = bOff + so;
#pragma unroll
        for (int ks = 0; ks < 2; ks++) {
            uint32_t a[4][4], b[4][2];
#pragma unroll
            for (int mi = 0; mi < 4; mi++)
                ldsm_x4(a[mi], aBase + (uint32_t)(mi * 16 * ASTRIDE + ks * 16) * 2);
#pragma unroll
            for (int nj = 0; nj < 2; nj++) {
                uint32_t r[4];
                ldsm_x4(r, bBase + (uint32_t)(nj * 16 * ASTRIDE + ks * 16) * 2);
                b[nj * 2][0] = r[0]; b[nj * 2][1] = r[1];
                b[nj * 2 + 1][0] = r[2]; b[nj * 2 + 1][1] = r[3];
            }
#pragma unroll
            for (int mi = 0; mi < 4; mi++)
#pragma unroll
                for (int ni = 0; ni < 4; ni++)
                    mma16816(acc[mi][ni], a[mi], b[ni]);
        }
    }

    // ---- fused epilogue ----
    // Padded columns (last block only): acc == 0.0 and relS == 0 exactly, so
    // ex2(0) == 1.0 exactly; we add them unguarded and subtract the count.
    const float pad_corr = (bn == NCB - 1) ? (float)(B_PAD - L_TOT) : 0.0f;
#pragma unroll
    for (int mi = 0; mi < 4; mi++) {
        const int rl0 = warp_row * 64 + mi * 16 + g;
        const int rl1 = rl0 + 8;
        const int lbl0 = lblS[rl0];
        const int lbl1 = lblS[rl1];
        float s0 = 0.0f, s1 = 0.0f;
#pragma unroll
        for (int ni = 0; ni < 4; ni++) {
#pragma unroll
            for (int h = 0; h < 2; h++) {
                const int lc = warp_col * 32 + ni * 8 + t * 2 + h;
                const int c = col0 + lc;
                const float rs = relS[lc];
                const float l0 = acc[mi][ni][h] * rs;      // log2-domain logit
                const float l1 = acc[mi][ni][2 + h] * rs;
                s0 += ex2f(l0);
                s1 += ex2f(l1);
                if (c == lbl0) g_labellogit2[row0 + rl0] = l0;   // unique writer
                if (c == lbl1) g_labellogit2[row0 + rl1] = l1;
            }
        }
        s0 += __shfl_xor_sync(0xFFFFFFFFu, s0, 1);
        s0 += __shfl_xor_sync(0xFFFFFFFFu, s0, 2);
        s1 += __shfl_xor_sync(0xFFFFFFFFu, s1, 1);
        s1 += __shfl_xor_sync(0xFFFFFFFFu, s1, 2);
        if (t == 0) {
            red[rl0 * 4 + warp_col] = s0;
            red[rl1 * 4 + warp_col] = s1;
        }
    }
    __syncthreads();
    if (tid < BM) {
        float s = red[tid * 4 + 0] + red[tid * 4 + 1]
                + red[tid * 4 + 2] + red[tid * 4 + 3];
        g_partial[bn][row0 + tid] = s - pad_corr;
    }
}

// ---------------------------------------------------------------------------
// Kernel 2: per-row loss + block reduction + last-block final reduce
// ---------------------------------------------------------------------------
__global__ __launch_bounds__(256)
void oim_rowloss_kernel(const int* __restrict__ label, float* __restrict__ out) {
    __shared__ float wsum[8], wcnt[8];
    __shared__ unsigned int is_last;
    const int i = blockIdx.x * 256 + threadIdx.x;    // row id, 32*256 = 8192
    float s = 0.0f;
#pragma unroll 4
    for (int b = 0; b < NCB; b++)
        s += g_partial[b][i];
    const int lbl = label[i];
    const bool valid = (lbl != IGNORE_IDX);
    // label logit stored in log2 units -> convert with ln2
    float loss = valid ? (logf(s) - g_labellogit2[i] * LN2F) : 0.0f;
    float cnt  = valid ? 1.0f : 0.0f;
#pragma unroll
    for (int off = 16; off > 0; off >>= 1) {
        loss += __shfl_down_sync(0xFFFFFFFFu, loss, off);
        cnt  += __shfl_down_sync(0xFFFFFFFFu, cnt, off);
    }
    const int lane = threadIdx.x & 31;
    const int w = threadIdx.x >> 5;
    if (lane == 0) { wsum[w] = loss; wcnt[w] = cnt; }
    __syncthreads();
    if (threadIdx.x == 0) {
        float bs = 0.0f, bc = 0.0f;
#pragma unroll
        for (int k = 0; k < 8; k++) { bs += wsum[k]; bc += wcnt[k]; }
        g_bsum[blockIdx.x] = bs;
        g_bcnt[blockIdx.x] = bc;
        __threadfence();
        unsigned int tk = atomicAdd(&g_ticket, 1u);
        is_last = (tk == 31u) ? 1u : 0u;
    }
    __syncthreads();
    if (is_last && threadIdx.x < 32) {
        __threadfence();
        float fs = ((volatile float*)g_bsum)[threadIdx.x];
        float fc = ((volatile float*)g_bcnt)[threadIdx.x];
#pragma unroll
        for (int off = 16; off > 0; off >>= 1) {
            fs += __shfl_down_sync(0xFFFFFFFFu, fs, off);
            fc += __shfl_down_sync(0xFFFFFFFFu, fc, off);
        }
        if (threadIdx.x == 0) {
            out[0] = fs / fmaxf(fc, 1.0f);
            g_ticket = 0u;              // reset for next replay
        }
    }
}

// ---------------------------------------------------------------------------
extern "C" void kernel_launch(void* const* d_in, const int* in_sizes, int n_in,
                              void* d_out, int out_size) {
    const float* inputs = (const float*)d_in[0];   // [8192, 256]
    const int*   label  = (const int*)  d_in[1];   // [8192]
    const float* lut    = (const float*)d_in[3];   // [5532, 256]
    const float* cq     = (const float*)d_in[4];   // [5000, 256]
    const float* rel    = (const float*)d_in[5];   // [10532]
    float* out = (float*)d_out;

    static bool attr_set = false;
    if (!attr_set) {
        cudaFuncSetAttribute(oim_mma_kernel,
                             cudaFuncAttributeMaxDynamicSharedMemorySize, SMEM_TOTAL);
        attr_set = true;
    }

    cvt_kernel<<<(QTR_F4 + 255) / 256, 256>>>(inputs, lut, cq);

    dim3 grid(NCB, N_ROWS / BM);   // 83 x 64
    oim_mma_kernel<<<grid, 256, SMEM_TOTAL>>>(rel, label);

    oim_rowloss_kernel<<<32, 256>>>(label, out);
}

// round 13
// speedup vs baseline: 1.1649x; 1.1649x over previous
#include <cuda_runtime.h>
#include <cuda_bf16.h>
#include <math.h>
#include <stdint.h>

// ---------------- problem constants ----------------
#define N_ROWS     8192
#define DIM        256
#define NUM_PIDS   5532
#define NUM_CQ     5000
#define L_TOT      (NUM_PIDS + NUM_CQ)   // 10532
#define IGNORE_IDX 5554
#define OIM_SCALAR 30.0f

// ---------------- tiling ----------------
#define BM 128
#define BN 128
#define BK 32
#define NSTAGE 4
#define NCB ((L_TOT + BN - 1) / BN)      // 83 column blocks
#define B_PAD (NCB * BN)                 // 10624 padded bank rows
#define ASTRIDE 40                       // bf16 elems per smem row (32 + 8 pad)

// dynamic smem layout (bytes)
#define STAGE_BYTES (BM * ASTRIDE * 2)          // 10240
#define OFF_SMA  0
#define OFF_SMB  (NSTAGE * STAGE_BYTES)         // 40960
#define OFF_REL  (2 * NSTAGE * STAGE_BYTES)     // 81920
#define OFF_LBL  (OFF_REL + BN * 4)             // 82432
#define OFF_RED  (OFF_LBL + BM * 4)             // 82944
#define SMEM_TOTAL (OFF_RED + BM * 4 * 4)       // 84992

// ---------------- device scratch (zero-initialized globals) ----------------
__device__ __nv_bfloat16 g_Abf[N_ROWS * DIM];
__device__ __nv_bfloat16 g_Bbf[B_PAD * DIM];   // rows >= L_TOT stay 0 forever
__device__ float g_partial[NCB][N_ROWS];
__device__ float g_labellogit[N_ROWS];
__device__ float g_bsum[32];
__device__ float g_bcnt[32];
__device__ unsigned int g_ticket;              // starts 0, reset by last block

// ---------------- PTX helpers (sm_80+, valid under compute_100) ----------
__device__ __forceinline__ uint32_t smem_u32(const void* p) {
    uint32_t a;
    asm("{ .reg .u64 t; cvta.to.shared.u64 t, %1; cvt.u32.u64 %0, t; }"
        : "=r"(a) : "l"(p));
    return a;
}
__device__ __forceinline__ void cp_async16(uint32_t dst, const void* src) {
    asm volatile("cp.async.cg.shared.global [%0], [%1], 16;"
                 :: "r"(dst), "l"(src) : "memory");
}
__device__ __forceinline__ void cp_commit() {
    asm volatile("cp.async.commit_group;" ::: "memory");
}
template <int N>
__device__ __forceinline__ void cp_wait() {
    asm volatile("cp.async.wait_group %0;" :: "n"(N) : "memory");
}
__device__ __forceinline__ void ldsm_x4(uint32_t* r, uint32_t addr) {
    asm volatile("ldmatrix.sync.aligned.m8n8.x4.shared.b16 {%0,%1,%2,%3}, [%4];"
                 : "=r"(r[0]), "=r"(r[1]), "=r"(r[2]), "=r"(r[3]) : "r"(addr));
}
__device__ __forceinline__ void mma16816(float* d, const uint32_t* a, const uint32_t* b) {
    asm volatile(
        "mma.sync.aligned.m16n8k16.row.col.f32.bf16.bf16.f32 "
        "{%0,%1,%2,%3}, {%4,%5,%6,%7}, {%8,%9}, {%0,%1,%2,%3};"
        : "+f"(d[0]), "+f"(d[1]), "+f"(d[2]), "+f"(d[3])
        : "r"(a[0]), "r"(a[1]), "r"(a[2]), "r"(a[3]), "r"(b[0]), "r"(b[1]));
}

// ---------------------------------------------------------------------------
// Kernel 0: fp32 -> bf16 conversion, 4 independent float4 chunks per thread
// ---------------------------------------------------------------------------
#define A_F4   (N_ROWS * DIM / 4)          // 524288
#define LUT_F4 (NUM_PIDS * DIM / 4)        // 354048
#define CQ_F4  (NUM_CQ * DIM / 4)          // 320000
#define TOT_F4 (A_F4 + LUT_F4 + CQ_F4)     // 1198336
#define QTR_F4 (TOT_F4 / 4)                // 299584

__device__ __forceinline__ void cvt_one(int i, const float* A,
                                        const float* lut, const float* cq) {
    const float4* src;
    __nv_bfloat16* dst;
    if (i < A_F4) {
        src = (const float4*)A + i;
        dst = g_Abf + (size_t)i * 4;
    } else if (i < A_F4 + LUT_F4) {
        int j = i - A_F4;
        src = (const float4*)lut + j;
        dst = g_Bbf + (size_t)j * 4;
    } else {
        int j = i - A_F4 - LUT_F4;
        src = (const float4*)cq + j;
        dst = g_Bbf + (size_t)(LUT_F4 + j) * 4;
    }
    float4 v = *src;
    ushort4 o;
    o.x = __bfloat16_as_ushort(__float2bfloat16_rn(v.x));
    o.y = __bfloat16_as_ushort(__float2bfloat16_rn(v.y));
    o.z = __bfloat16_as_ushort(__float2bfloat16_rn(v.z));
    o.w = __bfloat16_as_ushort(__float2bfloat16_rn(v.w));
    *reinterpret_cast<ushort4*>(dst) = o;
}

__global__ void cvt_kernel(const float* __restrict__ A,
                           const float* __restrict__ lut,
                           const float* __restrict__ cq) {
    int i = blockIdx.x * blockDim.x + threadIdx.x;
    if (i >= QTR_F4) return;
    cvt_one(i, A, lut, cq);
    cvt_one(i + QTR_F4, A, lut, cq);
    cvt_one(i + 2 * QTR_F4, A, lut, cq);
    cvt_one(i + 3 * QTR_F4, A, lut, cq);
}

// ---------------------------------------------------------------------------
// Kernel 1: mma.sync bf16 GEMM, 4-stage cp.async pipeline, fused exp-rowsum
// (R4 configuration; B fragments via ldmatrix.x4)
// ---------------------------------------------------------------------------
__global__ __launch_bounds__(256)
void oim_mma_kernel(const float* __restrict__ rel, const int* __restrict__ label)
{
    extern __shared__ __align__(16) char smem[];
    float* relS = (float*)(smem + OFF_REL);
    int*   lblS = (int*)(smem + OFF_LBL);
    float* red  = (float*)(smem + OFF_RED);

    const int tid = threadIdx.x;
    const int wid = tid >> 5;
    const int lane = tid & 31;
    const int warp_row = wid >> 2;        // 0..1
    const int warp_col = wid & 3;         // 0..3
    const int g = lane >> 2;
    const int t = lane & 3;

    const int bn = blockIdx.x;            // 0..82
    const int bm = blockIdx.y;            // 0..63
    const int row0 = bm * BM;
    const int col0 = bn * BN;

    if (tid < BN) {
        int c = col0 + tid;
        relS[tid] = (c < L_TOT) ? rel[c] * OIM_SCALAR : 0.0f;
    }
    if (tid < BM) lblS[tid] = label[row0 + tid];

    const uint32_t smA_u = smem_u32(smem + OFF_SMA);
    const uint32_t smB_u = smem_u32(smem + OFF_SMB);

    const int c0i = tid, c1i = tid + 256;
    const int m0 = c0i >> 2, ko0 = (c0i & 3) * 8;
    const int m1 = c1i >> 2, ko1 = (c1i & 3) * 8;
    const uint32_t dstA0 = smA_u + (uint32_t)(m0 * ASTRIDE + ko0) * 2;
    const uint32_t dstA1 = smA_u + (uint32_t)(m1 * ASTRIDE + ko1) * 2;
    const uint32_t dstB0 = smB_u + (uint32_t)(m0 * ASTRIDE + ko0) * 2;
    const uint32_t dstB1 = smB_u + (uint32_t)(m1 * ASTRIDE + ko1) * 2;
    const __nv_bfloat16* srcA0 = g_Abf + (size_t)(row0 + m0) * DIM + ko0;
    const __nv_bfloat16* srcA1 = g_Abf + (size_t)(row0 + m1) * DIM + ko1;
    const __nv_bfloat16* srcB0 = g_Bbf + (size_t)(col0 + m0) * DIM + ko0;
    const __nv_bfloat16* srcB1 = g_Bbf + (size_t)(col0 + m1) * DIM + ko1;

    // A ldmatrix x4: row = warp_row*64 + (lane&15), kofs = (lane>>4)*8
    const uint32_t aOff = smA_u +
        (uint32_t)(((warp_row * 64 + (lane & 15)) * ASTRIDE) + ((lane >> 4) << 3)) * 2;
    // B ldmatrix x4 (two n8 blocks per load): row = warp_col*32 + (lane&7) + ((lane&16)>>1),
    // kofs = ((lane>>3)&1)*8   (mapping verified by R5/R9/R10/R11 rel_err)
    const uint32_t bOff = smB_u +
        (uint32_t)(((warp_col * 32 + (lane & 7) + ((lane & 16) >> 1)) * ASTRIDE)
                   + (((lane >> 3) & 1) << 3)) * 2;

    float acc[4][4][4];
#pragma unroll
    for (int mi = 0; mi < 4; mi++)
#pragma unroll
        for (int ni = 0; ni < 4; ni++)
#pragma unroll
            for (int h = 0; h < 4; h++)
                acc[mi][ni][h] = 0.0f;

    // prologue: prefetch stages 0..2
#pragma unroll
    for (int s = 0; s < NSTAGE - 1; s++) {
        const uint32_t so = (uint32_t)s * STAGE_BYTES;
        const int gko = s * BK;
        cp_async16(dstA0 + so, srcA0 + gko);
        cp_async16(dstA1 + so, srcA1 + gko);
        cp_async16(dstB0 + so, srcB0 + gko);
        cp_async16(dstB1 + so, srcB1 + gko);
        cp_commit();
    }

#pragma unroll
    for (int kc = 0; kc < 8; kc++) {
        if (kc <= 5)      cp_wait<2>();
        else if (kc == 6) cp_wait<1>();
        else              cp_wait<0>();
        __syncthreads();

        if (kc < 5) {
            const uint32_t so = (uint32_t)((kc + 3) & (NSTAGE - 1)) * STAGE_BYTES;
            const int gko = (kc + 3) * BK;
            cp_async16(dstA0 + so, srcA0 + gko);
            cp_async16(dstA1 + so, srcA1 + gko);
            cp_async16(dstB0 + so, srcB0 + gko);
            cp_async16(dstB1 + so, srcB1 + gko);
            cp_commit();
        }

        const uint32_t so = (uint32_t)(kc & (NSTAGE - 1)) * STAGE_BYTES;
        const uint32_t aBase = aOff + so;
        const uint32_t bBase = bOff + so;
#pragma unroll
        for (int ks = 0; ks < 2; ks++) {
            uint32_t a[4][4], b[4][2];
#pragma unroll
            for (int mi = 0; mi < 4; mi++)
                ldsm_x4(a[mi], aBase + (uint32_t)(mi * 16 * ASTRIDE + ks * 16) * 2);
#pragma unroll
            for (int nj = 0; nj < 2; nj++) {
                uint32_t r[4];
                ldsm_x4(r, bBase + (uint32_t)(nj * 16 * ASTRIDE + ks * 16) * 2);
                b[nj * 2][0] = r[0]; b[nj * 2][1] = r[1];
                b[nj * 2 + 1][0] = r[2]; b[nj * 2 + 1][1] = r[3];
            }
#pragma unroll
            for (int mi = 0; mi < 4; mi++)
#pragma unroll
                for (int ni = 0; ni < 4; ni++)
                    mma16816(acc[mi][ni], a[mi], b[ni]);
        }
    }

    // ---- fused epilogue ----
#pragma unroll
    for (int mi = 0; mi < 4; mi++) {
        const int rl0 = warp_row * 64 + mi * 16 + g;
        const int rl1 = rl0 + 8;
        const int lbl0 = lblS[rl0];
        const int lbl1 = lblS[rl1];
        float s0 = 0.0f, s1 = 0.0f;
#pragma unroll
        for (int ni = 0; ni < 4; ni++) {
#pragma unroll
            for (int h = 0; h < 2; h++) {
                const int lc = warp_col * 32 + ni * 8 + t * 2 + h;
                const int c = col0 + lc;
                const float rs = relS[lc];
                const float l0 = acc[mi][ni][h] * rs;
                const float l1 = acc[mi][ni][2 + h] * rs;
                if (c < L_TOT) {
                    s0 += __expf(l0);
                    s1 += __expf(l1);
                }
                if (c == lbl0) g_labellogit[row0 + rl0] = l0;   // unique writer
                if (c == lbl1) g_labellogit[row0 + rl1] = l1;
            }
        }
        s0 += __shfl_xor_sync(0xFFFFFFFFu, s0, 1);
        s0 += __shfl_xor_sync(0xFFFFFFFFu, s0, 2);
        s1 += __shfl_xor_sync(0xFFFFFFFFu, s1, 1);
        s1 += __shfl_xor_sync(0xFFFFFFFFu, s1, 2);
        if (t == 0) {
            red[rl0 * 4 + warp_col] = s0;
            red[rl1 * 4 + warp_col] = s1;
        }
    }
    __syncthreads();
    if (tid < BM) {
        float s = red[tid * 4 + 0] + red[tid * 4 + 1]
                + red[tid * 4 + 2] + red[tid * 4 + 3];
        g_partial[bn][row0 + tid] = s;
    }
}

// ---------------------------------------------------------------------------
// Kernel 2: per-row loss + block reduction + last-block final reduce
// ---------------------------------------------------------------------------
__global__ __launch_bounds__(256)
void oim_rowloss_kernel(const int* __restrict__ label, float* __restrict__ out) {
    __shared__ float wsum[8], wcnt[8];
    __shared__ unsigned int is_last;
    const int i = blockIdx.x * 256 + threadIdx.x;    // row id, 32*256 = 8192
    float s = 0.0f;
#pragma unroll 4
    for (int b = 0; b < NCB; b++)
        s += g_partial[b][i];
    const int lbl = label[i];
    const bool valid = (lbl != IGNORE_IDX);
    float loss = valid ? (logf(s) - g_labellogit[i]) : 0.0f;
    float cnt  = valid ? 1.0f : 0.0f;
#pragma unroll
    for (int off = 16; off > 0; off >>= 1) {
        loss += __shfl_down_sync(0xFFFFFFFFu, loss, off);
        cnt  += __shfl_down_sync(0xFFFFFFFFu, cnt, off);
    }
    const int lane = threadIdx.x & 31;
    const int w = threadIdx.x >> 5;
    if (lane == 0) { wsum[w] = loss; wcnt[w] = cnt; }
    __syncthreads();
    if (threadIdx.x == 0) {
        float bs = 0.0f, bc = 0.0f;
#pragma unroll
        for (int k = 0; k < 8; k++) { bs += wsum[k]; bc += wcnt[k]; }
        g_bsum[blockIdx.x] = bs;
        g_bcnt[blockIdx.x] = bc;
        __threadfence();
        unsigned int tk = atomicAdd(&g_ticket, 1u);
        is_last = (tk == 31u) ? 1u : 0u;
    }
    __syncthreads();
    if (is_last && threadIdx.x < 32) {
        __threadfence();
        float fs = ((volatile float*)g_bsum)[threadIdx.x];
        float fc = ((volatile float*)g_bcnt)[threadIdx.x];
#pragma unroll
        for (int off = 16; off > 0; off >>= 1) {
            fs += __shfl_down_sync(0xFFFFFFFFu, fs, off);
            fc += __shfl_down_sync(0xFFFFFFFFu, fc, off);
        }
        if (threadIdx.x == 0) {
            out[0] = fs / fmaxf(fc, 1.0f);
            g_ticket = 0u;              // reset for next replay
        }
    }
}

// ---------------------------------------------------------------------------
extern "C" void kernel_launch(void* const* d_in, const int* in_sizes, int n_in,
                              void* d_out, int out_size) {
    const float* inputs = (const float*)d_in[0];   // [8192, 256]
    const int*   label  = (const int*)  d_in[1];   // [8192]
    const float* lut    = (const float*)d_in[3];   // [5532, 256]
    const float* cq     = (const float*)d_in[4];   // [5000, 256]
    const float* rel    = (const float*)d_in[5];   // [10532]
    float* out = (float*)d_out;

    static bool attr_set = false;
    if (!attr_set) {
        cudaFuncSetAttribute(oim_mma_kernel,
                             cudaFuncAttributeMaxDynamicSharedMemorySize, SMEM_TOTAL);
        attr_set = true;
    }

    cvt_kernel<<<(QTR_F4 + 255) / 256, 256>>>(inputs, lut, cq);

    dim3 grid(NCB, N_ROWS / BM);   // 83 x 64
    oim_mma_kernel<<<grid, 256, SMEM_TOTAL>>>(rel, label);

    oim_rowloss_kernel<<<32, 256>>>(label, out);
}

// round 14
// speedup vs baseline: 1.2485x; 1.0718x over previous
#include <cuda_runtime.h>
#include <cuda_bf16.h>
#include <math.h>
#include <stdint.h>

// ---------------- problem constants ----------------
#define N_ROWS     8192
#define DIM        256
#define NUM_PIDS   5532
#define NUM_CQ     5000
#define L_TOT      (NUM_PIDS + NUM_CQ)   // 10532
#define IGNORE_IDX 5554
#define OIM_SCALAR 30.0f

// ---------------- tiling ----------------
#define BM 128
#define BN 128
#define BK 32
#define NSTAGE 4
#define NCB ((L_TOT + BN - 1) / BN)      // 83 column blocks
#define B_PAD (NCB * BN)                 // 10624 padded bank rows
#define NPAD (B_PAD - L_TOT)             // 92 padded cols, all in last block
#define ASTRIDE 40                       // bf16 elems per smem row (32 + 8 pad)

// dynamic smem layout (bytes)
#define STAGE_BYTES (BM * ASTRIDE * 2)          // 10240
#define OFF_SMA  0
#define OFF_SMB  (NSTAGE * STAGE_BYTES)         // 40960
#define OFF_REL  (2 * NSTAGE * STAGE_BYTES)     // 81920
#define OFF_LBL  (OFF_REL + BN * 4)             // 82432
#define OFF_RED  (OFF_LBL + BM * 4)             // 82944
#define SMEM_TOTAL (OFF_RED + BM * 4 * 4)       // 84992

// ---------------- device scratch (zero-initialized globals) ----------------
__device__ __nv_bfloat16 g_Abf[N_ROWS * DIM];
__device__ __nv_bfloat16 g_Bbf[B_PAD * DIM];   // rows >= L_TOT stay 0 forever
__device__ float g_partial[NCB][N_ROWS];
__device__ float g_labellogit[N_ROWS];
__device__ float g_bsum[32];
__device__ float g_bcnt[32];
__device__ unsigned int g_ticket;              // starts 0, reset by last block

// ---------------- PTX helpers (sm_80+, valid under compute_100) ----------
__device__ __forceinline__ uint32_t smem_u32(const void* p) {
    uint32_t a;
    asm("{ .reg .u64 t; cvta.to.shared.u64 t, %1; cvt.u32.u64 %0, t; }"
        : "=r"(a) : "l"(p));
    return a;
}
__device__ __forceinline__ void cp_async16(uint32_t dst, const void* src) {
    asm volatile("cp.async.cg.shared.global [%0], [%1], 16;"
                 :: "r"(dst), "l"(src) : "memory");
}
__device__ __forceinline__ void cp_commit() {
    asm volatile("cp.async.commit_group;" ::: "memory");
}
template <int N>
__device__ __forceinline__ void cp_wait() {
    asm volatile("cp.async.wait_group %0;" :: "n"(N) : "memory");
}
__device__ __forceinline__ void ldsm_x4(uint32_t* r, uint32_t addr) {
    asm volatile("ldmatrix.sync.aligned.m8n8.x4.shared.b16 {%0,%1,%2,%3}, [%4];"
                 : "=r"(r[0]), "=r"(r[1]), "=r"(r[2]), "=r"(r[3]) : "r"(addr));
}
__device__ __forceinline__ void mma16816(float* d, const uint32_t* a, const uint32_t* b) {
    asm volatile(
        "mma.sync.aligned.m16n8k16.row.col.f32.bf16.bf16.f32 "
        "{%0,%1,%2,%3}, {%4,%5,%6,%7}, {%8,%9}, {%0,%1,%2,%3};"
        : "+f"(d[0]), "+f"(d[1]), "+f"(d[2]), "+f"(d[3])
        : "r"(a[0]), "r"(a[1]), "r"(a[2]), "r"(a[3]), "r"(b[0]), "r"(b[1]));
}

// ---------------------------------------------------------------------------
// Kernel 0: fp32 -> bf16 conversion, 4 independent float4 chunks per thread
// ---------------------------------------------------------------------------
#define A_F4   (N_ROWS * DIM / 4)          // 524288
#define LUT_F4 (NUM_PIDS * DIM / 4)        // 354048
#define CQ_F4  (NUM_CQ * DIM / 4)          // 320000
#define TOT_F4 (A_F4 + LUT_F4 + CQ_F4)     // 1198336
#define QTR_F4 (TOT_F4 / 4)                // 299584

__device__ __forceinline__ void cvt_one(int i, const float* A,
                                        const float* lut, const float* cq) {
    const float4* src;
    __nv_bfloat16* dst;
    if (i < A_F4) {
        src = (const float4*)A + i;
        dst = g_Abf + (size_t)i * 4;
    } else if (i < A_F4 + LUT_F4) {
        int j = i - A_F4;
        src = (const float4*)lut + j;
        dst = g_Bbf + (size_t)j * 4;
    } else {
        int j = i - A_F4 - LUT_F4;
        src = (const float4*)cq + j;
        dst = g_Bbf + (size_t)(LUT_F4 + j) * 4;
    }
    float4 v = *src;
    ushort4 o;
    o.x = __bfloat16_as_ushort(__float2bfloat16_rn(v.x));
    o.y = __bfloat16_as_ushort(__float2bfloat16_rn(v.y));
    o.z = __bfloat16_as_ushort(__float2bfloat16_rn(v.z));
    o.w = __bfloat16_as_ushort(__float2bfloat16_rn(v.w));
    *reinterpret_cast<ushort4*>(dst) = o;
}

__global__ void cvt_kernel(const float* __restrict__ A,
                           const float* __restrict__ lut,
                           const float* __restrict__ cq) {
    int i = blockIdx.x * blockDim.x + threadIdx.x;
    if (i >= QTR_F4) return;
    cvt_one(i, A, lut, cq);
    cvt_one(i + QTR_F4, A, lut, cq);
    cvt_one(i + 2 * QTR_F4, A, lut, cq);
    cvt_one(i + 3 * QTR_F4, A, lut, cq);
}

// ---------------------------------------------------------------------------
// Kernel 1: mma.sync bf16 GEMM, 4-stage cp.async pipeline, fused exp-rowsum
// (R13 GEMM; epilogue: unguarded exp accumulation with exact pad correction)
// ---------------------------------------------------------------------------
__global__ __launch_bounds__(256)
void oim_mma_kernel(const float* __restrict__ rel, const int* __restrict__ label)
{
    extern __shared__ __align__(16) char smem[];
    float* relS = (float*)(smem + OFF_REL);
    int*   lblS = (int*)(smem + OFF_LBL);
    float* red  = (float*)(smem + OFF_RED);

    const int tid = threadIdx.x;
    const int wid = tid >> 5;
    const int lane = tid & 31;
    const int warp_row = wid >> 2;        // 0..1
    const int warp_col = wid & 3;         // 0..3
    const int g = lane >> 2;
    const int t = lane & 3;

    const int bn = blockIdx.x;            // 0..82
    const int bm = blockIdx.y;            // 0..63
    const int row0 = bm * BM;
    const int col0 = bn * BN;

    if (tid < BN) {
        int c = col0 + tid;
        relS[tid] = (c < L_TOT) ? rel[c] * OIM_SCALAR : 0.0f;
    }
    if (tid < BM) lblS[tid] = label[row0 + tid];

    const uint32_t smA_u = smem_u32(smem + OFF_SMA);
    const uint32_t smB_u = smem_u32(smem + OFF_SMB);

    const int c0i = tid, c1i = tid + 256;
    const int m0 = c0i >> 2, ko0 = (c0i & 3) * 8;
    const int m1 = c1i >> 2, ko1 = (c1i & 3) * 8;
    const uint32_t dstA0 = smA_u + (uint32_t)(m0 * ASTRIDE + ko0) * 2;
    const uint32_t dstA1 = smA_u + (uint32_t)(m1 * ASTRIDE + ko1) * 2;
    const uint32_t dstB0 = smB_u + (uint32_t)(m0 * ASTRIDE + ko0) * 2;
    const uint32_t dstB1 = smB_u + (uint32_t)(m1 * ASTRIDE + ko1) * 2;
    const __nv_bfloat16* srcA0 = g_Abf + (size_t)(row0 + m0) * DIM + ko0;
    const __nv_bfloat16* srcA1 = g_Abf + (size_t)(row0 + m1) * DIM + ko1;
    const __nv_bfloat16* srcB0 = g_Bbf + (size_t)(col0 + m0) * DIM + ko0;
    const __nv_bfloat16* srcB1 = g_Bbf + (size_t)(col0 + m1) * DIM + ko1;

    // A ldmatrix x4: row = warp_row*64 + (lane&15), kofs = (lane>>4)*8
    const uint32_t aOff = smA_u +
        (uint32_t)(((warp_row * 64 + (lane & 15)) * ASTRIDE) + ((lane >> 4) << 3)) * 2;
    // B ldmatrix x4 (two n8 blocks per load)
    const uint32_t bOff = smB_u +
        (uint32_t)(((warp_col * 32 + (lane & 7) + ((lane & 16) >> 1)) * ASTRIDE)
                   + (((lane >> 3) & 1) << 3)) * 2;

    float acc[4][4][4];
#pragma unroll
    for (int mi = 0; mi < 4; mi++)
#pragma unroll
        for (int ni = 0; ni < 4; ni++)
#pragma unroll
            for (int h = 0; h < 4; h++)
                acc[mi][ni][h] = 0.0f;

    // prologue: prefetch stages 0..2
#pragma unroll
    for (int s = 0; s < NSTAGE - 1; s++) {
        const uint32_t so = (uint32_t)s * STAGE_BYTES;
        const int gko = s * BK;
        cp_async16(dstA0 + so, srcA0 + gko);
        cp_async16(dstA1 + so, srcA1 + gko);
        cp_async16(dstB0 + so, srcB0 + gko);
        cp_async16(dstB1 + so, srcB1 + gko);
        cp_commit();
    }

#pragma unroll
    for (int kc = 0; kc < 8; kc++) {
        if (kc <= 5)      cp_wait<2>();
        else if (kc == 6) cp_wait<1>();
        else              cp_wait<0>();
        __syncthreads();

        if (kc < 5) {
            const uint32_t so = (uint32_t)((kc + 3) & (NSTAGE - 1)) * STAGE_BYTES;
            const int gko = (kc + 3) * BK;
            cp_async16(dstA0 + so, srcA0 + gko);
            cp_async16(dstA1 + so, srcA1 + gko);
            cp_async16(dstB0 + so, srcB0 + gko);
            cp_async16(dstB1 + so, srcB1 + gko);
            cp_commit();
        }

        const uint32_t so = (uint32_t)(kc & (NSTAGE - 1)) * STAGE_BYTES;
        const uint32_t aBase = aOff + so;
        const uint32_t bBase = bOff + so;
#pragma unroll
        for (int ks = 0; ks < 2; ks++) {
            uint32_t a[4][4], b[4][2];
#pragma unroll
            for (int mi = 0; mi < 4; mi++)
                ldsm_x4(a[mi], aBase + (uint32_t)(mi * 16 * ASTRIDE + ks * 16) * 2);
#pragma unroll
            for (int nj = 0; nj < 2; nj++) {
                uint32_t r[4];
                ldsm_x4(r, bBase + (uint32_t)(nj * 16 * ASTRIDE + ks * 16) * 2);
                b[nj * 2][0] = r[0]; b[nj * 2][1] = r[1];
                b[nj * 2 + 1][0] = r[2]; b[nj * 2 + 1][1] = r[3];
            }
#pragma unroll
            for (int mi = 0; mi < 4; mi++)
#pragma unroll
                for (int ni = 0; ni < 4; ni++)
                    mma16816(acc[mi][ni], a[mi], b[ni]);
        }
    }

    // ---- fused epilogue ----
    // Padded columns (last block only): acc == 0.0 and relS == 0 exactly, so
    // __expf(0) == 1.0 exactly; accumulate unguarded and subtract the count.
    const float pad_corr = (bn == NCB - 1) ? (float)NPAD : 0.0f;
#pragma unroll
    for (int mi = 0; mi < 4; mi++) {
        const int rl0 = warp_row * 64 + mi * 16 + g;
        const int rl1 = rl0 + 8;
        const int lbl0 = lblS[rl0];
        const int lbl1 = lblS[rl1];
        float s0 = 0.0f, s1 = 0.0f;
#pragma unroll
        for (int ni = 0; ni < 4; ni++) {
#pragma unroll
            for (int h = 0; h < 2; h++) {
                const int lc = warp_col * 32 + ni * 8 + t * 2 + h;
                const int c = col0 + lc;
                const float rs = relS[lc];
                const float l0 = acc[mi][ni][h] * rs;
                const float l1 = acc[mi][ni][2 + h] * rs;
                s0 += __expf(l0);
                s1 += __expf(l1);
                if (c == lbl0) g_labellogit[row0 + rl0] = l0;   // unique writer
                if (c == lbl1) g_labellogit[row0 + rl1] = l1;
            }
        }
        s0 += __shfl_xor_sync(0xFFFFFFFFu, s0, 1);
        s0 += __shfl_xor_sync(0xFFFFFFFFu, s0, 2);
        s1 += __shfl_xor_sync(0xFFFFFFFFu, s1, 1);
        s1 += __shfl_xor_sync(0xFFFFFFFFu, s1, 2);
        if (t == 0) {
            red[rl0 * 4 + warp_col] = s0;
            red[rl1 * 4 + warp_col] = s1;
        }
    }
    __syncthreads();
    if (tid < BM) {
        float s = red[tid * 4 + 0] + red[tid * 4 + 1]
                + red[tid * 4 + 2] + red[tid * 4 + 3];
        g_partial[bn][row0 + tid] = s - pad_corr;
    }
}

// ---------------------------------------------------------------------------
// Kernel 2: per-row loss + block reduction + last-block final reduce
// ---------------------------------------------------------------------------
__global__ __launch_bounds__(256)
void oim_rowloss_kernel(const int* __restrict__ label, float* __restrict__ out) {
    __shared__ float wsum[8], wcnt[8];
    __shared__ unsigned int is_last;
    const int i = blockIdx.x * 256 + threadIdx.x;    // row id, 32*256 = 8192
    float s = 0.0f;
#pragma unroll 4
    for (int b = 0; b < NCB; b++)
        s += g_partial[b][i];
    const int lbl = label[i];
    const bool valid = (lbl != IGNORE_IDX);
    float loss = valid ? (logf(s) - g_labellogit[i]) : 0.0f;
    float cnt  = valid ? 1.0f : 0.0f;
#pragma unroll
    for (int off = 16; off > 0; off >>= 1) {
        loss += __shfl_down_sync(0xFFFFFFFFu, loss, off);
        cnt  += __shfl_down_sync(0xFFFFFFFFu, cnt, off);
    }
    const int lane = threadIdx.x & 31;
    const int w = threadIdx.x >> 5;
    if (lane == 0) { wsum[w] = loss; wcnt[w] = cnt; }
    __syncthreads();
    if (threadIdx.x == 0) {
        float bs = 0.0f, bc = 0.0f;
#pragma unroll
        for (int k = 0; k < 8; k++) { bs += wsum[k]; bc += wcnt[k]; }
        g_bsum[blockIdx.x] = bs;
        g_bcnt[blockIdx.x] = bc;
        __threadfence();
        unsigned int tk = atomicAdd(&g_ticket, 1u);
        is_last = (tk == 31u) ? 1u : 0u;
    }
    __syncthreads();
    if (is_last && threadIdx.x < 32) {
        __threadfence();
        float fs = ((volatile float*)g_bsum)[threadIdx.x];
        float fc = ((volatile float*)g_bcnt)[threadIdx.x];
#pragma unroll
        for (int off = 16; off > 0; off >>= 1) {
            fs += __shfl_down_sync(0xFFFFFFFFu, fs, off);
            fc += __shfl_down_sync(0xFFFFFFFFu, fc, off);
        }
        if (threadIdx.x == 0) {
            out[0] = fs / fmaxf(fc, 1.0f);
            g_ticket = 0u;              // reset for next replay
        }
    }
}

// ---------------------------------------------------------------------------
extern "C" void kernel_launch(void* const* d_in, const int* in_sizes, int n_in,
                              void* d_out, int out_size) {
    const float* inputs = (const float*)d_in[0];   // [8192, 256]
    const int*   label  = (const int*)  d_in[1];   // [8192]
    const float* lut    = (const float*)d_in[3];   // [5532, 256]
    const float* cq     = (const float*)d_in[4];   // [5000, 256]
    const float* rel    = (const float*)d_in[5];   // [10532]
    float* out = (float*)d_out;

    static bool attr_set = false;
    if (!attr_set) {
        cudaFuncSetAttribute(oim_mma_kernel,
                             cudaFuncAttributeMaxDynamicSharedMemorySize, SMEM_TOTAL);
        attr_set = true;
    }

    cvt_kernel<<<(QTR_F4 + 255) / 256, 256>>>(inputs, lut, cq);

    dim3 grid(NCB, N_ROWS / BM);   // 83 x 64
    oim_mma_kernel<<<grid, 256, SMEM_TOTAL>>>(rel, label);

    oim_rowloss_kernel<<<32, 256>>>(label, out);
}

// round 15
// speedup vs baseline: 1.3631x; 1.0918x over previous
#include <cuda_runtime.h>
#include <cuda_bf16.h>
#include <math.h>
#include <stdint.h>

// ---------------- problem constants ----------------
#define N_ROWS     8192
#define DIM        256
#define NUM_PIDS   5532
#define NUM_CQ     5000
#define L_TOT      (NUM_PIDS + NUM_CQ)   // 10532
#define IGNORE_IDX 5554
#define OIM_SCALAR 30.0f

// ---------------- tiling ----------------
#define BM 128
#define BN 128
#define BK 32
#define NSTAGE 4
#define NCB ((L_TOT + BN - 1) / BN)      // 83 column blocks
#define B_PAD (NCB * BN)                 // 10624 padded bank rows
#define NPAD (B_PAD - L_TOT)             // 92 padded cols, all in last block
#define ASTRIDE 40                       // bf16 elems per smem row (32 + 8 pad)

// dynamic smem layout (bytes)
#define STAGE_BYTES (BM * ASTRIDE * 2)          // 10240
#define OFF_SMA  0
#define OFF_SMB  (NSTAGE * STAGE_BYTES)         // 40960
#define OFF_REL  (2 * NSTAGE * STAGE_BYTES)     // 81920
#define OFF_RED  (OFF_REL + BN * 4)             // 82432
#define SMEM_TOTAL (OFF_RED + BM * 4 * 4)       // 84480

// rowloss config
#define RL_BLOCKS 1024                   // 8 warps/block, 1 row per warp

// ---------------- device scratch (zero-initialized globals) ----------------
__device__ __nv_bfloat16 g_Abf[N_ROWS * DIM];
__device__ __nv_bfloat16 g_Bbf[B_PAD * DIM];   // rows >= L_TOT stay 0 forever
__device__ float g_partial[NCB][N_ROWS];
__device__ float g_bsum[RL_BLOCKS];
__device__ float g_bcnt[RL_BLOCKS];
__device__ unsigned int g_ticket;              // starts 0, reset by last block

// ---------------- PTX helpers (sm_80+, valid under compute_100) ----------
__device__ __forceinline__ uint32_t smem_u32(const void* p) {
    uint32_t a;
    asm("{ .reg .u64 t; cvta.to.shared.u64 t, %1; cvt.u32.u64 %0, t; }"
        : "=r"(a) : "l"(p));
    return a;
}
__device__ __forceinline__ void cp_async16(uint32_t dst, const void* src) {
    asm volatile("cp.async.cg.shared.global [%0], [%1], 16;"
                 :: "r"(dst), "l"(src) : "memory");
}
__device__ __forceinline__ void cp_commit() {
    asm volatile("cp.async.commit_group;" ::: "memory");
}
template <int N>
__device__ __forceinline__ void cp_wait() {
    asm volatile("cp.async.wait_group %0;" :: "n"(N) : "memory");
}
__device__ __forceinline__ void ldsm_x4(uint32_t* r, uint32_t addr) {
    asm volatile("ldmatrix.sync.aligned.m8n8.x4.shared.b16 {%0,%1,%2,%3}, [%4];"
                 : "=r"(r[0]), "=r"(r[1]), "=r"(r[2]), "=r"(r[3]) : "r"(addr));
}
__device__ __forceinline__ void mma16816(float* d, const uint32_t* a, const uint32_t* b) {
    asm volatile(
        "mma.sync.aligned.m16n8k16.row.col.f32.bf16.bf16.f32 "
        "{%0,%1,%2,%3}, {%4,%5,%6,%7}, {%8,%9}, {%0,%1,%2,%3};"
        : "+f"(d[0]), "+f"(d[1]), "+f"(d[2]), "+f"(d[3])
        : "r"(a[0]), "r"(a[1]), "r"(a[2]), "r"(a[3]), "r"(b[0]), "r"(b[1]));
}

// ---------------------------------------------------------------------------
// Kernel 0: fp32 -> bf16 conversion, 4 independent float4 chunks per thread
// ---------------------------------------------------------------------------
#define A_F4   (N_ROWS * DIM / 4)          // 524288
#define LUT_F4 (NUM_PIDS * DIM / 4)        // 354048
#define CQ_F4  (NUM_CQ * DIM / 4)          // 320000
#define TOT_F4 (A_F4 + LUT_F4 + CQ_F4)     // 1198336
#define QTR_F4 (TOT_F4 / 4)                // 299584

__device__ __forceinline__ void cvt_one(int i, const float* A,
                                        const float* lut, const float* cq) {
    const float4* src;
    __nv_bfloat16* dst;
    if (i < A_F4) {
        src = (const float4*)A + i;
        dst = g_Abf + (size_t)i * 4;
    } else if (i < A_F4 + LUT_F4) {
        int j = i - A_F4;
        src = (const float4*)lut + j;
        dst = g_Bbf + (size_t)j * 4;
    } else {
        int j = i - A_F4 - LUT_F4;
        src = (const float4*)cq + j;
        dst = g_Bbf + (size_t)(LUT_F4 + j) * 4;
    }
    float4 v = *src;
    ushort4 o;
    o.x = __bfloat16_as_ushort(__float2bfloat16_rn(v.x));
    o.y = __bfloat16_as_ushort(__float2bfloat16_rn(v.y));
    o.z = __bfloat16_as_ushort(__float2bfloat16_rn(v.z));
    o.w = __bfloat16_as_ushort(__float2bfloat16_rn(v.w));
    *reinterpret_cast<ushort4*>(dst) = o;
}

__global__ void cvt_kernel(const float* __restrict__ A,
                           const float* __restrict__ lut,
                           const float* __restrict__ cq) {
    int i = blockIdx.x * blockDim.x + threadIdx.x;
    if (i >= QTR_F4) return;
    cvt_one(i, A, lut, cq);
    cvt_one(i + QTR_F4, A, lut, cq);
    cvt_one(i + 2 * QTR_F4, A, lut, cq);
    cvt_one(i + 3 * QTR_F4, A, lut, cq);
}

// ---------------------------------------------------------------------------
// Kernel 1: mma.sync bf16 GEMM, 4-stage cp.async pipeline, fused exp-rowsum
// (epilogue: unguarded, no label capture, rel in registers)
// ---------------------------------------------------------------------------
__global__ __launch_bounds__(256)
void oim_mma_kernel(const float* __restrict__ rel)
{
    extern __shared__ __align__(16) char smem[];
    float* relS = (float*)(smem + OFF_REL);
    float* red  = (float*)(smem + OFF_RED);

    const int tid = threadIdx.x;
    const int wid = tid >> 5;
    const int lane = tid & 31;
    const int warp_row = wid >> 2;        // 0..1
    const int warp_col = wid & 3;         // 0..3
    const int g = lane >> 2;
    const int t = lane & 3;

    const int bn = blockIdx.x;            // 0..82
    const int bm = blockIdx.y;            // 0..63
    const int row0 = bm * BM;
    const int col0 = bn * BN;

    if (tid < BN) {
        int c = col0 + tid;
        relS[tid] = (c < L_TOT) ? rel[c] * OIM_SCALAR : 0.0f;
    }

    const uint32_t smA_u = smem_u32(smem + OFF_SMA);
    const uint32_t smB_u = smem_u32(smem + OFF_SMB);

    const int c0i = tid, c1i = tid + 256;
    const int m0 = c0i >> 2, ko0 = (c0i & 3) * 8;
    const int m1 = c1i >> 2, ko1 = (c1i & 3) * 8;
    const uint32_t dstA0 = smA_u + (uint32_t)(m0 * ASTRIDE + ko0) * 2;
    const uint32_t dstA1 = smA_u + (uint32_t)(m1 * ASTRIDE + ko1) * 2;
    const uint32_t dstB0 = smB_u + (uint32_t)(m0 * ASTRIDE + ko0) * 2;
    const uint32_t dstB1 = smB_u + (uint32_t)(m1 * ASTRIDE + ko1) * 2;
    const __nv_bfloat16* srcA0 = g_Abf + (size_t)(row0 + m0) * DIM + ko0;
    const __nv_bfloat16* srcA1 = g_Abf + (size_t)(row0 + m1) * DIM + ko1;
    const __nv_bfloat16* srcB0 = g_Bbf + (size_t)(col0 + m0) * DIM + ko0;
    const __nv_bfloat16* srcB1 = g_Bbf + (size_t)(col0 + m1) * DIM + ko1;

    // A ldmatrix x4: row = warp_row*64 + (lane&15), kofs = (lane>>4)*8
    const uint32_t aOff = smA_u +
        (uint32_t)(((warp_row * 64 + (lane & 15)) * ASTRIDE) + ((lane >> 4) << 3)) * 2;
    // B ldmatrix x4 (two n8 blocks per load)
    const uint32_t bOff = smB_u +
        (uint32_t)(((warp_col * 32 + (lane & 7) + ((lane & 16) >> 1)) * ASTRIDE)
                   + (((lane >> 3) & 1) << 3)) * 2;

    float acc[4][4][4];
#pragma unroll
    for (int mi = 0; mi < 4; mi++)
#pragma unroll
        for (int ni = 0; ni < 4; ni++)
#pragma unroll
            for (int h = 0; h < 4; h++)
                acc[mi][ni][h] = 0.0f;

    // prologue: prefetch stages 0..2
#pragma unroll
    for (int s = 0; s < NSTAGE - 1; s++) {
        const uint32_t so = (uint32_t)s * STAGE_BYTES;
        const int gko = s * BK;
        cp_async16(dstA0 + so, srcA0 + gko);
        cp_async16(dstA1 + so, srcA1 + gko);
        cp_async16(dstB0 + so, srcB0 + gko);
        cp_async16(dstB1 + so, srcB1 + gko);
        cp_commit();
    }

#pragma unroll
    for (int kc = 0; kc < 8; kc++) {
        if (kc <= 5)      cp_wait<2>();
        else if (kc == 6) cp_wait<1>();
        else              cp_wait<0>();
        __syncthreads();

        if (kc < 5) {
            const uint32_t so = (uint32_t)((kc + 3) & (NSTAGE - 1)) * STAGE_BYTES;
            const int gko = (kc + 3) * BK;
            cp_async16(dstA0 + so, srcA0 + gko);
            cp_async16(dstA1 + so, srcA1 + gko);
            cp_async16(dstB0 + so, srcB0 + gko);
            cp_async16(dstB1 + so, srcB1 + gko);
            cp_commit();
        }

        const uint32_t so = (uint32_t)(kc & (NSTAGE - 1)) * STAGE_BYTES;
        const uint32_t aBase = aOff + so;
        const uint32_t bBase = bOff + so;
#pragma unroll
        for (int ks = 0; ks < 2; ks++) {
            uint32_t a[4][4], b[4][2];
#pragma unroll
            for (int mi = 0; mi < 4; mi++)
                ldsm_x4(a[mi], aBase + (uint32_t)(mi * 16 * ASTRIDE + ks * 16) * 2);
#pragma unroll
            for (int nj = 0; nj < 2; nj++) {
                uint32_t r[4];
                ldsm_x4(r, bBase + (uint32_t)(nj * 16 * ASTRIDE + ks * 16) * 2);
                b[nj * 2][0] = r[0]; b[nj * 2][1] = r[1];
                b[nj * 2 + 1][0] = r[2]; b[nj * 2 + 1][1] = r[3];
            }
#pragma unroll
            for (int mi = 0; mi < 4; mi++)
#pragma unroll
                for (int ni = 0; ni < 4; ni++)
                    mma16816(acc[mi][ni], a[mi], b[ni]);
        }
    }

    // ---- fused epilogue: pure exp row-sums (no guards, no label capture) ----
    // Padded cols: acc == 0 and relS == 0 exactly -> __expf(0) == 1.0 exactly;
    // accumulate unguarded and subtract the exact count in the last block.
    const float pad_corr = (bn == NCB - 1) ? (float)NPAD : 0.0f;

    // hoist this thread's 8 rel values into registers (red[] stores below
    // would otherwise block LDS CSE across mi iterations)
    float rsv[8];
#pragma unroll
    for (int ni = 0; ni < 4; ni++)
#pragma unroll
        for (int h = 0; h < 2; h++)
            rsv[ni * 2 + h] = relS[warp_col * 32 + ni * 8 + t * 2 + h];

#pragma unroll
    for (int mi = 0; mi < 4; mi++) {
        const int rl0 = warp_row * 64 + mi * 16 + g;
        const int rl1 = rl0 + 8;
        float s0 = 0.0f, s1 = 0.0f;
#pragma unroll
        for (int ni = 0; ni < 4; ni++) {
#pragma unroll
            for (int h = 0; h < 2; h++) {
                const float rs = rsv[ni * 2 + h];
                s0 += __expf(acc[mi][ni][h] * rs);
                s1 += __expf(acc[mi][ni][2 + h] * rs);
            }
        }
        s0 += __shfl_xor_sync(0xFFFFFFFFu, s0, 1);
        s0 += __shfl_xor_sync(0xFFFFFFFFu, s0, 2);
        s1 += __shfl_xor_sync(0xFFFFFFFFu, s1, 1);
        s1 += __shfl_xor_sync(0xFFFFFFFFu, s1, 2);
        if (t == 0) {
            red[rl0 * 4 + warp_col] = s0;
            red[rl1 * 4 + warp_col] = s1;
        }
    }
    __syncthreads();
    if (tid < BM) {
        float s = red[tid * 4 + 0] + red[tid * 4 + 1]
                + red[tid * 4 + 2] + red[tid * 4 + 3];
        g_partial[bn][row0 + tid] = s - pad_corr;
    }
}

// ---------------------------------------------------------------------------
// Kernel 2: warp-per-row loss (partial-sum + label-logit dot) + final reduce
// ---------------------------------------------------------------------------
__global__ __launch_bounds__(256)
void oim_rowloss_kernel(const int* __restrict__ label,
                        const float* __restrict__ rel,
                        float* __restrict__ out) {
    __shared__ float wsum[8], wcnt[8];
    __shared__ unsigned int is_last;
    const int wid = threadIdx.x >> 5;
    const int lane = threadIdx.x & 31;
    const int row = blockIdx.x * 8 + wid;          // 1024 blocks x 8 warps

    // partial sum of exp over column blocks (fixed assignment: lane, lane+32, lane+64)
    float s = 0.0f;
#pragma unroll
    for (int b = lane; b < NCB; b += 32)
        s += g_partial[b][row];

    const int lbl = label[row];
    // label-logit dot over bf16 inputs: lane covers 8 elements
    const uint4 av = *reinterpret_cast<const uint4*>(
        g_Abf + (size_t)row * DIM + lane * 8);
    const uint4 bv = *reinterpret_cast<const uint4*>(
        g_Bbf + (size_t)lbl * DIM + lane * 8);
    float d = 0.0f;
    {
        const __nv_bfloat162* ap = reinterpret_cast<const __nv_bfloat162*>(&av);
        const __nv_bfloat162* bp = reinterpret_cast<const __nv_bfloat162*>(&bv);
#pragma unroll
        for (int k = 0; k < 4; k++) {
            float2 af = __bfloat1622float2(ap[k]);
            float2 bf = __bfloat1622float2(bp[k]);
            d = fmaf(af.x, bf.x, d);
            d = fmaf(af.y, bf.y, d);
        }
    }
    // joint shuffle reduce
#pragma unroll
    for (int off = 16; off > 0; off >>= 1) {
        s += __shfl_down_sync(0xFFFFFFFFu, s, off);
        d += __shfl_down_sync(0xFFFFFFFFu, d, off);
    }
    if (lane == 0) {
        const bool valid = (lbl != IGNORE_IDX);
        float ll = d * (rel[lbl] * OIM_SCALAR);
        wsum[wid] = valid ? (logf(s) - ll) : 0.0f;
        wcnt[wid] = valid ? 1.0f : 0.0f;
    }
    __syncthreads();
    if (threadIdx.x == 0) {
        float bs = 0.0f, bc = 0.0f;
#pragma unroll
        for (int k = 0; k < 8; k++) { bs += wsum[k]; bc += wcnt[k]; }
        g_bsum[blockIdx.x] = bs;
        g_bcnt[blockIdx.x] = bc;
        __threadfence();
        unsigned int tk = atomicAdd(&g_ticket, 1u);
        is_last = (tk == RL_BLOCKS - 1) ? 1u : 0u;
    }
    __syncthreads();
    if (is_last) {
        __threadfence();
        // 256 threads x 4 entries each
        float fs = 0.0f, fc = 0.0f;
#pragma unroll
        for (int k = 0; k < 4; k++) {
            int idx = threadIdx.x + k * 256;
            fs += ((volatile float*)g_bsum)[idx];
            fc += ((volatile float*)g_bcnt)[idx];
        }
#pragma unroll
        for (int off = 16; off > 0; off >>= 1) {
            fs += __shfl_down_sync(0xFFFFFFFFu, fs, off);
            fc += __shfl_down_sync(0xFFFFFFFFu, fc, off);
        }
        if (lane == 0) { wsum[wid] = fs; wcnt[wid] = fc; }
        __syncthreads();
        if (threadIdx.x == 0) {
            float ts = 0.0f, tc = 0.0f;
#pragma unroll
            for (int k = 0; k < 8; k++) { ts += wsum[k]; tc += wcnt[k]; }
            out[0] = ts / fmaxf(tc, 1.0f);
            g_ticket = 0u;              // reset for next replay
        }
    }
}

// ---------------------------------------------------------------------------
extern "C" void kernel_launch(void* const* d_in, const int* in_sizes, int n_in,
                              void* d_out, int out_size) {
    const float* inputs = (const float*)d_in[0];   // [8192, 256]
    const int*   label  = (const int*)  d_in[1];   // [8192]
    const float* lut    = (const float*)d_in[3];   // [5532, 256]
    const float* cq     = (const float*)d_in[4];   // [5000, 256]
    const float* rel    = (const float*)d_in[5];   // [10532]
    float* out = (float*)d_out;

    static bool attr_set = false;
    if (!attr_set) {
        cudaFuncSetAttribute(oim_mma_kernel,
                             cudaFuncAttributeMaxDynamicSharedMemorySize, SMEM_TOTAL);
        attr_set = true;
    }

    cvt_kernel<<<(QTR_F4 + 255) / 256, 256>>>(inputs, lut, cq);

    dim3 grid(NCB, N_ROWS / BM);   // 83 x 64
    oim_mma_kernel<<<grid, 256, SMEM_TOTAL>>>(rel);

    oim_rowloss_kernel<<<RL_BLOCKS, 256>>>(label, rel, out);
}

// round 16
// speedup vs baseline: 1.3841x; 1.0154x over previous
#include <cuda_runtime.h>
#include <cuda_bf16.h>
#include <math.h>
#include <stdint.h>

// ---------------- problem constants ----------------
#define N_ROWS     8192
#define DIM        256
#define NUM_PIDS   5532
#define NUM_CQ     5000
#define L_TOT      (NUM_PIDS + NUM_CQ)   // 10532
#define IGNORE_IDX 5554
#define OIM_SCALAR 30.0f

// ---------------- tiling ----------------
#define BM 128
#define BN 128
#define BK 32
#define NSTAGE 4
#define NCB ((L_TOT + BN - 1) / BN)      // 83 column blocks
#define B_PAD (NCB * BN)                 // 10624 padded bank rows
#define NPAD (B_PAD - L_TOT)             // 92 padded cols, all in last block
#define ASTRIDE 40                       // bf16 elems per smem row (32 + 8 pad)

// dynamic smem layout (bytes)
#define STAGE_BYTES (BM * ASTRIDE * 2)          // 10240
#define OFF_SMA  0
#define OFF_SMB  (NSTAGE * STAGE_BYTES)         // 40960
#define OFF_RED  (2 * NSTAGE * STAGE_BYTES)     // 81920
#define SMEM_TOTAL (OFF_RED + BM * 4 * 4)       // 83968

// rowloss config
#define RL_BLOCKS 1024                   // 8 warps/block, 1 row per warp

// ---------------- device scratch (zero-initialized globals) ----------------
__device__ __nv_bfloat16 g_Abf[N_ROWS * DIM];
__device__ __nv_bfloat16 g_Bbf[B_PAD * DIM];   // PRE-SCALED by rel*30; pad rows stay 0
__device__ float g_partial[NCB][N_ROWS];
__device__ float g_bsum[RL_BLOCKS];
__device__ float g_bcnt[RL_BLOCKS];
__device__ unsigned int g_ticket;              // starts 0, reset by last block

// ---------------- PTX helpers (sm_80+, valid under compute_100) ----------
__device__ __forceinline__ uint32_t smem_u32(const void* p) {
    uint32_t a;
    asm("{ .reg .u64 t; cvta.to.shared.u64 t, %1; cvt.u32.u64 %0, t; }"
        : "=r"(a) : "l"(p));
    return a;
}
__device__ __forceinline__ void cp_async16(uint32_t dst, const void* src) {
    asm volatile("cp.async.cg.shared.global [%0], [%1], 16;"
                 :: "r"(dst), "l"(src) : "memory");
}
__device__ __forceinline__ void cp_commit() {
    asm volatile("cp.async.commit_group;" ::: "memory");
}
template <int N>
__device__ __forceinline__ void cp_wait() {
    asm volatile("cp.async.wait_group %0;" :: "n"(N) : "memory");
}
__device__ __forceinline__ void ldsm_x4(uint32_t* r, uint32_t addr) {
    asm volatile("ldmatrix.sync.aligned.m8n8.x4.shared.b16 {%0,%1,%2,%3}, [%4];"
                 : "=r"(r[0]), "=r"(r[1]), "=r"(r[2]), "=r"(r[3]) : "r"(addr));
}
__device__ __forceinline__ void mma16816(float* d, const uint32_t* a, const uint32_t* b) {
    asm volatile(
        "mma.sync.aligned.m16n8k16.row.col.f32.bf16.bf16.f32 "
        "{%0,%1,%2,%3}, {%4,%5,%6,%7}, {%8,%9}, {%0,%1,%2,%3};"
        : "+f"(d[0]), "+f"(d[1]), "+f"(d[2]), "+f"(d[3])
        : "r"(a[0]), "r"(a[1]), "r"(a[2]), "r"(a[3]), "r"(b[0]), "r"(b[1]));
}

// ---------------------------------------------------------------------------
// Kernel 0: fp32 -> bf16 conversion; B rows pre-scaled by rel[c] * 30
// ---------------------------------------------------------------------------
#define A_F4   (N_ROWS * DIM / 4)          // 524288
#define LUT_F4 (NUM_PIDS * DIM / 4)        // 354048
#define CQ_F4  (NUM_CQ * DIM / 4)          // 320000
#define TOT_F4 (A_F4 + LUT_F4 + CQ_F4)     // 1198336
#define QTR_F4 (TOT_F4 / 4)                // 299584
#define F4_PER_ROW (DIM / 4)               // 64

__device__ __forceinline__ void cvt_one(int i, const float* A,
                                        const float* lut, const float* cq,
                                        const float* rel) {
    const float4* src;
    __nv_bfloat16* dst;
    float scale;
    if (i < A_F4) {
        src = (const float4*)A + i;
        dst = g_Abf + (size_t)i * 4;
        scale = 1.0f;
    } else if (i < A_F4 + LUT_F4) {
        int j = i - A_F4;
        src = (const float4*)lut + j;
        dst = g_Bbf + (size_t)j * 4;
        scale = rel[j / F4_PER_ROW] * OIM_SCALAR;
    } else {
        int j = i - A_F4 - LUT_F4;
        src = (const float4*)cq + j;
        dst = g_Bbf + (size_t)(LUT_F4 + j) * 4;
        scale = rel[NUM_PIDS + j / F4_PER_ROW] * OIM_SCALAR;
    }
    float4 v = *src;
    ushort4 o;
    o.x = __bfloat16_as_ushort(__float2bfloat16_rn(v.x * scale));
    o.y = __bfloat16_as_ushort(__float2bfloat16_rn(v.y * scale));
    o.z = __bfloat16_as_ushort(__float2bfloat16_rn(v.z * scale));
    o.w = __bfloat16_as_ushort(__float2bfloat16_rn(v.w * scale));
    *reinterpret_cast<ushort4*>(dst) = o;
}

__global__ void cvt_kernel(const float* __restrict__ A,
                           const float* __restrict__ lut,
                           const float* __restrict__ cq,
                           const float* __restrict__ rel) {
    int i = blockIdx.x * blockDim.x + threadIdx.x;
    if (i >= QTR_F4) return;
    cvt_one(i, A, lut, cq, rel);
    cvt_one(i + QTR_F4, A, lut, cq, rel);
    cvt_one(i + 2 * QTR_F4, A, lut, cq, rel);
    cvt_one(i + 3 * QTR_F4, A, lut, cq, rel);
}

// ---------------------------------------------------------------------------
// Kernel 1: mma.sync bf16 GEMM, 4-stage cp.async pipeline, fused exp-rowsum
// (B pre-scaled: epilogue is pure exp + reduce; no rel, no guards, no labels)
// ---------------------------------------------------------------------------
__global__ __launch_bounds__(256)
void oim_mma_kernel()
{
    extern __shared__ __align__(16) char smem[];
    float* red = (float*)(smem + OFF_RED);

    const int tid = threadIdx.x;
    const int wid = tid >> 5;
    const int lane = tid & 31;
    const int warp_row = wid >> 2;        // 0..1
    const int warp_col = wid & 3;         // 0..3
    const int g = lane >> 2;
    const int t = lane & 3;

    const int bn = blockIdx.x;            // 0..82
    const int bm = blockIdx.y;            // 0..63
    const int row0 = bm * BM;
    const int col0 = bn * BN;

    const uint32_t smA_u = smem_u32(smem + OFF_SMA);
    const uint32_t smB_u = smem_u32(smem + OFF_SMB);

    const int c0i = tid, c1i = tid + 256;
    const int m0 = c0i >> 2, ko0 = (c0i & 3) * 8;
    const int m1 = c1i >> 2, ko1 = (c1i & 3) * 8;
    const uint32_t dstA0 = smA_u + (uint32_t)(m0 * ASTRIDE + ko0) * 2;
    const uint32_t dstA1 = smA_u + (uint32_t)(m1 * ASTRIDE + ko1) * 2;
    const uint32_t dstB0 = smB_u + (uint32_t)(m0 * ASTRIDE + ko0) * 2;
    const uint32_t dstB1 = smB_u + (uint32_t)(m1 * ASTRIDE + ko1) * 2;
    const __nv_bfloat16* srcA0 = g_Abf + (size_t)(row0 + m0) * DIM + ko0;
    const __nv_bfloat16* srcA1 = g_Abf + (size_t)(row0 + m1) * DIM + ko1;
    const __nv_bfloat16* srcB0 = g_Bbf + (size_t)(col0 + m0) * DIM + ko0;
    const __nv_bfloat16* srcB1 = g_Bbf + (size_t)(col0 + m1) * DIM + ko1;

    // A ldmatrix x4: row = warp_row*64 + (lane&15), kofs = (lane>>4)*8
    const uint32_t aOff = smA_u +
        (uint32_t)(((warp_row * 64 + (lane & 15)) * ASTRIDE) + ((lane >> 4) << 3)) * 2;
    // B ldmatrix x4 (two n8 blocks per load)
    const uint32_t bOff = smB_u +
        (uint32_t)(((warp_col * 32 + (lane & 7) + ((lane & 16) >> 1)) * ASTRIDE)
                   + (((lane >> 3) & 1) << 3)) * 2;

    float acc[4][4][4];
#pragma unroll
    for (int mi = 0; mi < 4; mi++)
#pragma unroll
        for (int ni = 0; ni < 4; ni++)
#pragma unroll
            for (int h = 0; h < 4; h++)
                acc[mi][ni][h] = 0.0f;

    // prologue: prefetch stages 0..2
#pragma unroll
    for (int s = 0; s < NSTAGE - 1; s++) {
        const uint32_t so = (uint32_t)s * STAGE_BYTES;
        const int gko = s * BK;
        cp_async16(dstA0 + so, srcA0 + gko);
        cp_async16(dstA1 + so, srcA1 + gko);
        cp_async16(dstB0 + so, srcB0 + gko);
        cp_async16(dstB1 + so, srcB1 + gko);
        cp_commit();
    }

#pragma unroll
    for (int kc = 0; kc < 8; kc++) {
        if (kc <= 5)      cp_wait<2>();
        else if (kc == 6) cp_wait<1>();
        else              cp_wait<0>();
        __syncthreads();

        if (kc < 5) {
            const uint32_t so = (uint32_t)((kc + 3) & (NSTAGE - 1)) * STAGE_BYTES;
            const int gko = (kc + 3) * BK;
            cp_async16(dstA0 + so, srcA0 + gko);
            cp_async16(dstA1 + so, srcA1 + gko);
            cp_async16(dstB0 + so, srcB0 + gko);
            cp_async16(dstB1 + so, srcB1 + gko);
            cp_commit();
        }

        const uint32_t so = (uint32_t)(kc & (NSTAGE - 1)) * STAGE_BYTES;
        const uint32_t aBase = aOff + so;
        const uint32_t bBase = bOff + so;
#pragma unroll
        for (int ks = 0; ks < 2; ks++) {
            uint32_t a[4][4], b[4][2];
#pragma unroll
            for (int mi = 0; mi < 4; mi++)
                ldsm_x4(a[mi], aBase + (uint32_t)(mi * 16 * ASTRIDE + ks * 16) * 2);
#pragma unroll
            for (int nj = 0; nj < 2; nj++) {
                uint32_t r[4];
                ldsm_x4(r, bBase + (uint32_t)(nj * 16 * ASTRIDE + ks * 16) * 2);
                b[nj * 2][0] = r[0]; b[nj * 2][1] = r[1];
                b[nj * 2 + 1][0] = r[2]; b[nj * 2 + 1][1] = r[3];
            }
#pragma unroll
            for (int mi = 0; mi < 4; mi++)
#pragma unroll
                for (int ni = 0; ni < 4; ni++)
                    mma16816(acc[mi][ni], a[mi], b[ni]);
        }
    }

    // ---- fused epilogue: logits are the raw accumulators (B pre-scaled) ----
    // Padded cols: acc == 0 exactly -> __expf(0) == 1.0 exactly; accumulate
    // unguarded and subtract the exact count in the last block.
    const float pad_corr = (bn == NCB - 1) ? (float)NPAD : 0.0f;
#pragma unroll
    for (int mi = 0; mi < 4; mi++) {
        const int rl0 = warp_row * 64 + mi * 16 + g;
        const int rl1 = rl0 + 8;
        float s0 = 0.0f, s1 = 0.0f;
#pragma unroll
        for (int ni = 0; ni < 4; ni++) {
#pragma unroll
            for (int h = 0; h < 2; h++) {
                s0 += __expf(acc[mi][ni][h]);
                s1 += __expf(acc[mi][ni][2 + h]);
            }
        }
        s0 += __shfl_xor_sync(0xFFFFFFFFu, s0, 1);
        s0 += __shfl_xor_sync(0xFFFFFFFFu, s0, 2);
        s1 += __shfl_xor_sync(0xFFFFFFFFu, s1, 1);
        s1 += __shfl_xor_sync(0xFFFFFFFFu, s1, 2);
        if (t == 0) {
            red[rl0 * 4 + warp_col] = s0;
            red[rl1 * 4 + warp_col] = s1;
        }
    }
    __syncthreads();
    if (tid < BM) {
        float s = red[tid * 4 + 0] + red[tid * 4 + 1]
                + red[tid * 4 + 2] + red[tid * 4 + 3];
        g_partial[bn][row0 + tid] = s - pad_corr;
    }
}

// ---------------------------------------------------------------------------
// Kernel 2: warp-per-row loss (partial-sum + label-logit dot) + final reduce
// (label logit = dot(A_row, Bscaled_label) directly — B carries rel*30)
// ---------------------------------------------------------------------------
__global__ __launch_bounds__(256)
void oim_rowloss_kernel(const int* __restrict__ label, float* __restrict__ out) {
    __shared__ float wsum[8], wcnt[8];
    __shared__ unsigned int is_last;
    const int wid = threadIdx.x >> 5;
    const int lane = threadIdx.x & 31;
    const int row = blockIdx.x * 8 + wid;          // 1024 blocks x 8 warps

    // partial sum of exp over column blocks
    float s = 0.0f;
#pragma unroll
    for (int b = lane; b < NCB; b += 32)
        s += g_partial[b][row];

    const int lbl = label[row];
    // label-logit dot over bf16 inputs (B pre-scaled): lane covers 8 elements
    const uint4 av = *reinterpret_cast<const uint4*>(
        g_Abf + (size_t)row * DIM + lane * 8);
    const uint4 bv = *reinterpret_cast<const uint4*>(
        g_Bbf + (size_t)lbl * DIM + lane * 8);
    float d = 0.0f;
    {
        const __nv_bfloat162* ap = reinterpret_cast<const __nv_bfloat162*>(&av);
        const __nv_bfloat162* bp = reinterpret_cast<const __nv_bfloat162*>(&bv);
#pragma unroll
        for (int k = 0; k < 4; k++) {
            float2 af = __bfloat1622float2(ap[k]);
            float2 bf = __bfloat1622float2(bp[k]);
            d = fmaf(af.x, bf.x, d);
            d = fmaf(af.y, bf.y, d);
        }
    }
#pragma unroll
    for (int off = 16; off > 0; off >>= 1) {
        s += __shfl_down_sync(0xFFFFFFFFu, s, off);
        d += __shfl_down_sync(0xFFFFFFFFu, d, off);
    }
    if (lane == 0) {
        const bool valid = (lbl != IGNORE_IDX);
        wsum[wid] = valid ? (logf(s) - d) : 0.0f;
        wcnt[wid] = valid ? 1.0f : 0.0f;
    }
    __syncthreads();
    if (threadIdx.x == 0) {
        float bs = 0.0f, bc = 0.0f;
#pragma unroll
        for (int k = 0; k < 8; k++) { bs += wsum[k]; bc += wcnt[k]; }
        g_bsum[blockIdx.x] = bs;
        g_bcnt[blockIdx.x] = bc;
        __threadfence();
        unsigned int tk = atomicAdd(&g_ticket, 1u);
        is_last = (tk == RL_BLOCKS - 1) ? 1u : 0u;
    }
    __syncthreads();
    if (is_last) {
        __threadfence();
        float fs = 0.0f, fc = 0.0f;
#pragma unroll
        for (int k = 0; k < 4; k++) {
            int idx = threadIdx.x + k * 256;
            fs += ((volatile float*)g_bsum)[idx];
            fc += ((volatile float*)g_bcnt)[idx];
        }
#pragma unroll
        for (int off = 16; off > 0; off >>= 1) {
            fs += __shfl_down_sync(0xFFFFFFFFu, fs, off);
            fc += __shfl_down_sync(0xFFFFFFFFu, fc, off);
        }
        if (lane == 0) { wsum[wid] = fs; wcnt[wid] = fc; }
        __syncthreads();
        if (threadIdx.x == 0) {
            float ts = 0.0f, tc = 0.0f;
#pragma unroll
            for (int k = 0; k < 8; k++) { ts += wsum[k]; tc += wcnt[k]; }
            out[0] = ts / fmaxf(tc, 1.0f);
            g_ticket = 0u;              // reset for next replay
        }
    }
}

// ---------------------------------------------------------------------------
extern "C" void kernel_launch(void* const* d_in, const int* in_sizes, int n_in,
                              void* d_out, int out_size) {
    const float* inputs = (const float*)d_in[0];   // [8192, 256]
    const int*   label  = (const int*)  d_in[1];   // [8192]
    const float* lut    = (const float*)d_in[3];   // [5532, 256]
    const float* cq     = (const float*)d_in[4];   // [5000, 256]
    const float* rel    = (const float*)d_in[5];   // [10532]
    float* out = (float*)d_out;

    static bool attr_set = false;
    if (!attr_set) {
        cudaFuncSetAttribute(oim_mma_kernel,
                             cudaFuncAttributeMaxDynamicSharedMemorySize, SMEM_TOTAL);
        attr_set = true;
    }

    cvt_kernel<<<(QTR_F4 + 255) / 256, 256>>>(inputs, lut, cq, rel);

    dim3 grid(NCB, N_ROWS / BM);   // 83 x 64
    oim_mma_kernel<<<grid, 256, SMEM_TOTAL>>>();

    oim_rowloss_kernel<<<RL_BLOCKS, 256>>>(label, out);
}